// round 3
// baseline (speedup 1.0000x reference)
#include <cuda_runtime.h>
#include <math.h>

// Problem dims (fixed by setup_inputs)
#define ND 50000
#define FD 128
#define NC 10000
#define FC 735
#define ED 800000
#define EC 160000
#define BATCH 16384

// ------------------------- scratch (device globals) -------------------------
__device__ float g_d0[ND * 256];      // drug features after MLP
__device__ float g_dx[ND * 256];      // drug GAT x = d @ gdW
__device__ float g_dagg[ND * 256];    // drug GAT aggregation / output
__device__ float g_c0[NC * 1024];     // cell after cW1
__device__ float g_c1[NC * 256];      // cell after cW2
__device__ float g_cx1[NC * 1024];    // cell GAT1 x
__device__ float g_cagg1[NC * 1024];  // cell GAT1 agg/out
__device__ float g_cx2[NC * 256];     // cell GAT2 x
__device__ float g_cagg2[NC * 256];   // cell GAT2 agg/out
__device__ float g_as[ND];            // per-node attention src scores
__device__ float g_ad[ND];            // per-node attention dst scores
__device__ unsigned g_m[ND];          // encoded segment max
__device__ float g_den[ND];           // softmax denominator
__device__ float g_ex[ED + ND];       // per-edge exp values
__device__ float g_comb[BATCH * 512];
__device__ float g_h1[BATCH * 512];
__device__ float g_h2[BATCH * 512];

// ------------------------- helpers -------------------------
__device__ __forceinline__ unsigned enc_f32(float f) {
    unsigned u = __float_as_uint(f);
    return (u & 0x80000000u) ? ~u : (u | 0x80000000u);
}
__device__ __forceinline__ float dec_f32(unsigned u) {
    return (u & 0x80000000u) ? __uint_as_float(u ^ 0x80000000u)
                             : __uint_as_float(~u);
}

// ------------------------- SGEMM: C = act(A@B + bias) -------------------------
// A [M,K] row-major, B [K,N] row-major. 64x64 tile, BK=16, 256 threads, 4x4/thread.
// act: 0 = none, 1 = relu, 2 = elu
__global__ void sgemm_kernel(const float* __restrict__ A, const float* __restrict__ B,
                             const float* __restrict__ bias, float* __restrict__ C,
                             int M, int N, int K, int act) {
    __shared__ float As[16][65];
    __shared__ float Bs[16][64];
    const int tid = threadIdx.x;
    const int tx = tid & 15, ty = tid >> 4;
    const int mbase = blockIdx.y * 64, nbase = blockIdx.x * 64;

    float acc[4][4] = {};

    for (int k0 = 0; k0 < K; k0 += 16) {
#pragma unroll
        for (int j = 0; j < 4; j++) {
            int idx = tid + j * 256;   // 0..1023
            // A tile: As[k][m]
            int m = idx >> 4;
            int kk = idx & 15;
            int gm = mbase + m, gk = k0 + kk;
            As[kk][m] = (gm < M && gk < K) ? A[(size_t)gm * K + gk] : 0.f;
            // B tile: Bs[k][n]
            int kb = idx >> 6;
            int nn = idx & 63;
            int gn = nbase + nn, gk2 = k0 + kb;
            Bs[kb][nn] = (gn < N && gk2 < K) ? B[(size_t)gk2 * N + gn] : 0.f;
        }
        __syncthreads();
#pragma unroll
        for (int kk = 0; kk < 16; kk++) {
            float a[4], b[4];
#pragma unroll
            for (int i = 0; i < 4; i++) a[i] = As[kk][ty * 4 + i];
#pragma unroll
            for (int j = 0; j < 4; j++) b[j] = Bs[kk][tx * 4 + j];
#pragma unroll
            for (int i = 0; i < 4; i++)
#pragma unroll
                for (int j = 0; j < 4; j++) acc[i][j] = fmaf(a[i], b[j], acc[i][j]);
        }
        __syncthreads();
    }

#pragma unroll
    for (int i = 0; i < 4; i++) {
        int gm = mbase + ty * 4 + i;
        if (gm >= M) continue;
#pragma unroll
        for (int j = 0; j < 4; j++) {
            int gn = nbase + tx * 4 + j;
            if (gn >= N) continue;
            float v = acc[i][j];
            if (bias) v += bias[gn];
            if (act == 1) v = v > 0.f ? v : 0.f;
            else if (act == 2) v = v > 0.f ? v : (expf(v) - 1.f);
            C[(size_t)gm * N + gn] = v;
        }
    }
}

// ------------------------- GAT pieces -------------------------
// Per-node dots: out_s[n] = x[n,:]·asrc, out_d[n] = x[n,:]·adst  (warp/node)
__global__ void node_dots_kernel(const float* __restrict__ x,
                                 const float* __restrict__ asrc,
                                 const float* __restrict__ adst,
                                 float* __restrict__ out_s, float* __restrict__ out_d,
                                 int n, int F) {
    int w = (int)((blockIdx.x * (size_t)blockDim.x + threadIdx.x) >> 5);
    int lane = threadIdx.x & 31;
    if (w >= n) return;
    const float* xr = x + (size_t)w * F;
    float s = 0.f, d = 0.f;
    for (int f = lane; f < F; f += 32) {
        float v = xr[f];
        s = fmaf(v, asrc[f], s);
        d = fmaf(v, adst[f], d);
    }
#pragma unroll
    for (int o = 16; o; o >>= 1) {
        s += __shfl_xor_sync(0xffffffffu, s, o);
        d += __shfl_xor_sync(0xffffffffu, d, o);
    }
    if (lane == 0) { out_s[w] = s; out_d[w] = d; }
}

// Segment max of leaky_relu(a_s[src]+a_d[dst]) over dst. Work item i in [0, E+n).
__global__ void edge_max_kernel(const int* __restrict__ ei, int E, int n,
                                const float* __restrict__ as_, const float* __restrict__ ad_,
                                unsigned* __restrict__ m) {
    int i = blockIdx.x * blockDim.x + threadIdx.x;
    if (i >= E + n) return;
    int s, d;
    if (i < E) { s = ei[i]; d = ei[E + i]; } else { s = d = i - E; }
    float e = as_[s] + ad_[d];
    e = e > 0.f ? e : 0.2f * e;
    atomicMax(&m[d], enc_f32(e));
}

// ex[i] = exp(e - m[dst]); denom[dst] += ex
__global__ void edge_exp_kernel(const int* __restrict__ ei, int E, int n,
                                const float* __restrict__ as_, const float* __restrict__ ad_,
                                const unsigned* __restrict__ m,
                                float* __restrict__ ex, float* __restrict__ den) {
    int i = blockIdx.x * blockDim.x + threadIdx.x;
    if (i >= E + n) return;
    int s, d;
    if (i < E) { s = ei[i]; d = ei[E + i]; } else { s = d = i - E; }
    float e = as_[s] + ad_[d];
    e = e > 0.f ? e : 0.2f * e;
    float v = expf(e - dec_f32(m[d]));
    ex[i] = v;
    atomicAdd(&den[d], v);
}

// out[dst,:] += (ex/den[dst]) * x[src,:]   (warp per edge)
__global__ void edge_agg_kernel(const int* __restrict__ ei, int E, int n,
                                const float* __restrict__ ex, const float* __restrict__ den,
                                const float* __restrict__ x, float* __restrict__ out, int F) {
    size_t gt = blockIdx.x * (size_t)blockDim.x + threadIdx.x;
    int w = (int)(gt >> 5);
    int lane = threadIdx.x & 31;
    if (w >= E + n) return;
    int s, d;
    if (w < E) { s = ei[w]; d = ei[E + w]; } else { s = d = w - E; }
    float alpha = ex[w] / den[d];
    const float* xr = x + (size_t)s * F;
    float* orow = out + (size_t)d * F;
    for (int f = lane; f < F; f += 32)
        atomicAdd(&orow[f], alpha * xr[f]);
}

// p = relu(p + bias)
__global__ void bias_relu_kernel(float* __restrict__ p, const float* __restrict__ b,
                                 int n, int F) {
    size_t i = blockIdx.x * (size_t)blockDim.x + threadIdx.x;
    if (i >= (size_t)n * F) return;
    float v = p[i] + b[i % F];
    p[i] = v > 0.f ? v : 0.f;
}

// comb[b] = [d[drug_idx[b]], c[cell_idx[b]]]
__global__ void gather_comb_kernel(const float* __restrict__ dsrc, const float* __restrict__ csrc,
                                   const int* __restrict__ di, const int* __restrict__ ci,
                                   float* __restrict__ comb) {
    int b = blockIdx.x;
    int t = threadIdx.x;  // 256 threads
    comb[(size_t)b * 512 + t] = dsrc[(size_t)di[b] * 256 + t];
    comb[(size_t)b * 512 + 256 + t] = csrc[(size_t)ci[b] * 256 + t];
}

// out[r] = h[r,:512]·W[:,0] + b[0]   (warp per row)
__global__ void head_final_kernel(const float* __restrict__ h, const float* __restrict__ W,
                                  const float* __restrict__ b, float* __restrict__ out) {
    size_t gt = blockIdx.x * (size_t)blockDim.x + threadIdx.x;
    int r = (int)(gt >> 5);
    int lane = threadIdx.x & 31;
    if (r >= BATCH) return;
    const float* hr = h + (size_t)r * 512;
    float s = 0.f;
    for (int f = lane; f < 512; f += 32) s = fmaf(hr[f], W[f], s);
#pragma unroll
    for (int o = 16; o; o >>= 1) s += __shfl_xor_sync(0xffffffffu, s, o);
    if (lane == 0) out[r] = s + b[0];
}

// ------------------------- host side -------------------------
static inline void launch_sgemm(const float* A, const float* B, const float* bias,
                                float* C, int M, int N, int K, int act) {
    dim3 grid((N + 63) / 64, (M + 63) / 64);
    sgemm_kernel<<<grid, 256>>>(A, B, bias, C, M, N, K, act);
}

static void run_gat(const int* ei, int E, int n, int F,
                    const float* x,            // [n,F] projected features
                    const float* avec_s, const float* avec_d, const float* bias,
                    float* as_, float* ad_, unsigned* m, float* den, float* ex,
                    float* out /* [n,F], pre-zeroed */) {
    // node dots
    {
        size_t threads = (size_t)n * 32;
        node_dots_kernel<<<(unsigned)((threads + 255) / 256), 256>>>(x, avec_s, avec_d, as_, ad_, n, F);
    }
    int total = E + n;
    edge_max_kernel<<<(total + 255) / 256, 256>>>(ei, E, n, as_, ad_, m);
    edge_exp_kernel<<<(total + 255) / 256, 256>>>(ei, E, n, as_, ad_, m, ex, den);
    {
        size_t threads = (size_t)total * 32;
        edge_agg_kernel<<<(unsigned)((threads + 255) / 256), 256>>>(ei, E, n, ex, den, x, out, F);
    }
    bias_relu_kernel<<<(unsigned)(((size_t)n * F + 255) / 256), 256>>>(out, bias, n, F);
}

extern "C" void kernel_launch(void* const* d_in, const int* in_sizes, int n_in,
                              void* d_out, int out_size) {
    const float* drug_x = (const float*)d_in[0];
    const float* cell_x = (const float*)d_in[1];
    const int* dei = (const int*)d_in[2];
    const int* cei = (const int*)d_in[3];
    const int* didx = (const int*)d_in[4];
    const int* cidx = (const int*)d_in[5];
    const float* dW1 = (const float*)d_in[6];  const float* db1 = (const float*)d_in[7];
    const float* cW1 = (const float*)d_in[8];  const float* cb1 = (const float*)d_in[9];
    const float* cW2 = (const float*)d_in[10]; const float* cb2 = (const float*)d_in[11];
    const float* gdW = (const float*)d_in[12]; const float* gdas = (const float*)d_in[13];
    const float* gdad = (const float*)d_in[14]; const float* gdb = (const float*)d_in[15];
    const float* g1W = (const float*)d_in[16]; const float* g1as = (const float*)d_in[17];
    const float* g1ad = (const float*)d_in[18]; const float* g1b = (const float*)d_in[19];
    const float* g2W = (const float*)d_in[20]; const float* g2as = (const float*)d_in[21];
    const float* g2ad = (const float*)d_in[22]; const float* g2b = (const float*)d_in[23];
    const float* rW1 = (const float*)d_in[24]; const float* rb1 = (const float*)d_in[25];
    const float* rW2 = (const float*)d_in[26]; const float* rb2 = (const float*)d_in[27];
    const float* rW3 = (const float*)d_in[28]; const float* rb3 = (const float*)d_in[29];
    float* out = (float*)d_out;

    float *p_d0, *p_dx, *p_dagg, *p_c0, *p_c1, *p_cx1, *p_cagg1, *p_cx2, *p_cagg2;
    float *p_as, *p_ad, *p_den, *p_ex, *p_comb, *p_h1, *p_h2;
    unsigned* p_m;
    cudaGetSymbolAddress((void**)&p_d0, g_d0);
    cudaGetSymbolAddress((void**)&p_dx, g_dx);
    cudaGetSymbolAddress((void**)&p_dagg, g_dagg);
    cudaGetSymbolAddress((void**)&p_c0, g_c0);
    cudaGetSymbolAddress((void**)&p_c1, g_c1);
    cudaGetSymbolAddress((void**)&p_cx1, g_cx1);
    cudaGetSymbolAddress((void**)&p_cagg1, g_cagg1);
    cudaGetSymbolAddress((void**)&p_cx2, g_cx2);
    cudaGetSymbolAddress((void**)&p_cagg2, g_cagg2);
    cudaGetSymbolAddress((void**)&p_as, g_as);
    cudaGetSymbolAddress((void**)&p_ad, g_ad);
    cudaGetSymbolAddress((void**)&p_m, g_m);
    cudaGetSymbolAddress((void**)&p_den, g_den);
    cudaGetSymbolAddress((void**)&p_ex, g_ex);
    cudaGetSymbolAddress((void**)&p_comb, g_comb);
    cudaGetSymbolAddress((void**)&p_h1, g_h1);
    cudaGetSymbolAddress((void**)&p_h2, g_h2);

    // ---- feature transforms ----
    launch_sgemm(drug_x, dW1, db1, p_d0, ND, 256, FD, 1);     // relu
    launch_sgemm(cell_x, cW1, cb1, p_c0, NC, 1024, FC, 1);    // relu
    launch_sgemm(p_c0, cW2, cb2, p_c1, NC, 256, 1024, 1);     // relu

    // ---- drug GAT (256 -> 256) ----
    launch_sgemm(p_d0, gdW, nullptr, p_dx, ND, 256, 256, 0);
    cudaMemsetAsync(p_m, 0, ND * sizeof(unsigned));
    cudaMemsetAsync(p_den, 0, ND * sizeof(float));
    cudaMemsetAsync(p_dagg, 0, (size_t)ND * 256 * sizeof(float));
    run_gat(dei, ED, ND, 256, p_dx, gdas, gdad, gdb, p_as, p_ad, p_m, p_den, p_ex, p_dagg);

    // ---- cell GAT1 (256 -> 1024) ----
    launch_sgemm(p_c1, g1W, nullptr, p_cx1, NC, 1024, 256, 0);
    cudaMemsetAsync(p_m, 0, NC * sizeof(unsigned));
    cudaMemsetAsync(p_den, 0, NC * sizeof(float));
    cudaMemsetAsync(p_cagg1, 0, (size_t)NC * 1024 * sizeof(float));
    run_gat(cei, EC, NC, 1024, p_cx1, g1as, g1ad, g1b, p_as, p_ad, p_m, p_den, p_ex, p_cagg1);

    // ---- cell GAT2 (1024 -> 256) ----
    launch_sgemm(p_cagg1, g2W, nullptr, p_cx2, NC, 256, 1024, 0);
    cudaMemsetAsync(p_m, 0, NC * sizeof(unsigned));
    cudaMemsetAsync(p_den, 0, NC * sizeof(float));
    cudaMemsetAsync(p_cagg2, 0, (size_t)NC * 256 * sizeof(float));
    run_gat(cei, EC, NC, 256, p_cx2, g2as, g2ad, g2b, p_as, p_ad, p_m, p_den, p_ex, p_cagg2);

    // ---- pair gather + regression head ----
    gather_comb_kernel<<<BATCH, 256>>>(p_dagg, p_cagg2, didx, cidx, p_comb);
    launch_sgemm(p_comb, rW1, rb1, p_h1, BATCH, 512, 512, 2);  // elu
    launch_sgemm(p_h1, rW2, rb2, p_h2, BATCH, 512, 512, 2);    // elu
    head_final_kernel<<<(BATCH * 32 + 255) / 256, 256>>>(p_h2, rW3, rb3, out);
}

// round 7
// speedup vs baseline: 1.0759x; 1.0759x over previous
#include <cuda_runtime.h>
#include <math.h>

// Problem dims (fixed by setup_inputs)
#define ND 50000
#define FD 128
#define NC 10000
#define FC 735
#define FCP 736        // padded K for cell MLP1
#define ED 800000
#define EC 160000
#define BATCH 16384

// ------------------------- scratch (device globals) -------------------------
__device__ float g_d0[ND * 256];
__device__ float g_dx[ND * 256];
__device__ float g_dagg[ND * 256];
__device__ float g_c0[NC * 1024];
__device__ float g_c1[NC * 256];
__device__ float g_cx1[NC * 1024];
__device__ float g_cagg1[NC * 1024];
__device__ float g_cx2[NC * 256];
__device__ float g_cagg2[NC * 256];
__device__ float g_as[ND];
__device__ float g_ad[ND];
__device__ float g_alpha[ED + ND];
__device__ int   g_off[ND + 1];
__device__ int   g_cnt[ND];
__device__ int   g_bsum[64];
__device__ int   g_csrc[ED + ND];
__device__ float g_cxp[NC * FCP];      // padded cell_x
__device__ float g_w1p[FCP * 1024];    // padded cW1
__device__ float g_comb[BATCH * 512];
__device__ float g_h1[BATCH * 512];
__device__ float g_h2[BATCH * 512];

// ------------------------- SGEMM -------------------------
// C[M,N] = act(A[M,K] @ B[K,N] + bias). Row-major. BN=128, BK=8, 256 threads.
// Requires: K % 8 == 0, N % 128 == 0.  act: 0 none, 1 relu, 2 elu.
template<int BM, int TM>
__global__ __launch_bounds__(256, 2)
void sgemm2_kernel(const float* __restrict__ A, const float* __restrict__ B,
                   const float* __restrict__ bias, float* __restrict__ C,
                   int M, int N, int K, int act) {
    __shared__ float As[2][8][BM];
    __shared__ float Bs[2][8][128];
    const int tid = threadIdx.x;
    const int tx = tid & 15;        // col group (0..15), 8 cols each
    const int ty = tid >> 4;        // row group (0..15), TM rows each
    const int mbase = blockIdx.y * BM;
    const int nbase = blockIdx.x * 128;

    const int arow = tid >> 1;          // A: 2 threads per row (8 k / 4)
    const int ak   = (tid & 1) * 4;
    const int brow = tid >> 5;          // B: 32 threads per k-row
    const int bcol = (tid & 31) * 4;
    const bool aval = (BM == 128) || (tid < 128);

    float4 ra = make_float4(0.f, 0.f, 0.f, 0.f), rb;
    // prologue: tile 0
    {
        int gm = mbase + arow;
        if (aval && gm < M) ra = *(const float4*)&A[(size_t)gm * K + ak];
        rb = *(const float4*)&B[(size_t)brow * N + nbase + bcol];
    }
    if (aval) {
        As[0][ak + 0][arow] = ra.x; As[0][ak + 1][arow] = ra.y;
        As[0][ak + 2][arow] = ra.z; As[0][ak + 3][arow] = ra.w;
    }
    *(float4*)&Bs[0][brow][bcol] = rb;
    __syncthreads();

    float acc[TM][8];
#pragma unroll
    for (int i = 0; i < TM; i++)
#pragma unroll
        for (int j = 0; j < 8; j++) acc[i][j] = 0.f;

    const int nk = K >> 3;
    for (int t = 1; t <= nk; t++) {
        const int cur = (t - 1) & 1, nxt = t & 1;
        if (t < nk) {
            int k0 = t * 8;
            int gm = mbase + arow;
            ra = make_float4(0.f, 0.f, 0.f, 0.f);
            if (aval && gm < M) ra = *(const float4*)&A[(size_t)gm * K + k0 + ak];
            rb = *(const float4*)&B[(size_t)(k0 + brow) * N + nbase + bcol];
        }
#pragma unroll
        for (int k = 0; k < 8; k++) {
            float a[TM], b[8];
            float4 a0 = *(const float4*)&As[cur][k][ty * TM];
            a[0] = a0.x; a[1] = a0.y; a[2] = a0.z; a[3] = a0.w;
            if (TM == 8) {
                float4 a1 = *(const float4*)&As[cur][k][ty * TM + 4];
                a[4] = a1.x; a[5] = a1.y; a[6] = a1.z; a[7] = a1.w;
            }
            float4 b0 = *(const float4*)&Bs[cur][k][tx * 8];
            float4 b1 = *(const float4*)&Bs[cur][k][tx * 8 + 4];
            b[0] = b0.x; b[1] = b0.y; b[2] = b0.z; b[3] = b0.w;
            b[4] = b1.x; b[5] = b1.y; b[6] = b1.z; b[7] = b1.w;
#pragma unroll
            for (int i = 0; i < TM; i++)
#pragma unroll
                for (int j = 0; j < 8; j++)
                    acc[i][j] = fmaf(a[i], b[j], acc[i][j]);
        }
        if (t < nk) {
            if (aval) {
                As[nxt][ak + 0][arow] = ra.x; As[nxt][ak + 1][arow] = ra.y;
                As[nxt][ak + 2][arow] = ra.z; As[nxt][ak + 3][arow] = ra.w;
            }
            *(float4*)&Bs[nxt][brow][bcol] = rb;
        }
        __syncthreads();
    }

    // epilogue
    float bv[8];
    if (bias) {
        float4 q0 = *(const float4*)&bias[nbase + tx * 8];
        float4 q1 = *(const float4*)&bias[nbase + tx * 8 + 4];
        bv[0] = q0.x; bv[1] = q0.y; bv[2] = q0.z; bv[3] = q0.w;
        bv[4] = q1.x; bv[5] = q1.y; bv[6] = q1.z; bv[7] = q1.w;
    } else {
#pragma unroll
        for (int j = 0; j < 8; j++) bv[j] = 0.f;
    }
#pragma unroll
    for (int i = 0; i < TM; i++) {
        int gm = mbase + ty * TM + i;
        if (gm >= M) break;
        float o[8];
#pragma unroll
        for (int j = 0; j < 8; j++) {
            float v = acc[i][j] + bv[j];
            if (act == 1) v = v > 0.f ? v : 0.f;
            else if (act == 2) v = v > 0.f ? v : (expf(v) - 1.f);
            o[j] = v;
        }
        float* crow = C + (size_t)gm * N + nbase + tx * 8;
        *(float4*)&crow[0] = make_float4(o[0], o[1], o[2], o[3]);
        *(float4*)&crow[4] = make_float4(o[4], o[5], o[6], o[7]);
    }
}

static inline void sgemm128(const float* A, const float* B, const float* bias,
                            float* C, int M, int N, int K, int act) {
    dim3 g(N / 128, (M + 127) / 128);
    sgemm2_kernel<128, 8><<<g, 256>>>(A, B, bias, C, M, N, K, act);
}
static inline void sgemm64(const float* A, const float* B, const float* bias,
                           float* C, int M, int N, int K, int act) {
    dim3 g(N / 128, (M + 63) / 64);
    sgemm2_kernel<64, 4><<<g, 256>>>(A, B, bias, C, M, N, K, act);
}

// ------------------------- padding kernels -------------------------
__global__ void pad_cellx_kernel(const float* __restrict__ src, float* __restrict__ dst) {
    int i = blockIdx.x * blockDim.x + threadIdx.x;
    if (i >= NC * FCP) return;
    int r = i / FCP, k = i - r * FCP;
    dst[i] = (k < FC) ? src[(size_t)r * FC + k] : 0.f;
}
__global__ void pad_w1_kernel(const float* __restrict__ src, float* __restrict__ dst) {
    int i = blockIdx.x * blockDim.x + threadIdx.x;
    if (i >= FCP * 1024) return;
    int k = i >> 10;
    dst[i] = (k < FC) ? src[i] : 0.f;   // same layout for k < FC
}

// ------------------------- CSR build -------------------------
__global__ void hist_kernel(const int* __restrict__ ei, int E, int n, int* __restrict__ cnt) {
    int i = blockIdx.x * blockDim.x + threadIdx.x;
    if (i >= E + n) return;
    int d = (i < E) ? ei[E + i] : (i - E);
    atomicAdd(&cnt[d], 1);
}

__global__ void scan_block_kernel(const int* __restrict__ cnt, int* __restrict__ off,
                                  int* __restrict__ bsum, int n) {
    __shared__ int sh[1024];
    int t = threadIdx.x;
    int i = blockIdx.x * 1024 + t;
    int v = (i < n) ? cnt[i] : 0;
    sh[t] = v;
    __syncthreads();
    for (int o = 1; o < 1024; o <<= 1) {
        int x = (t >= o) ? sh[t - o] : 0;
        __syncthreads();
        sh[t] += x;
        __syncthreads();
    }
    if (i < n) off[i] = sh[t] - v;          // exclusive
    if (t == 1023) bsum[blockIdx.x] = sh[t];
}

__global__ void scan_add_kernel(int* __restrict__ off, const int* __restrict__ bsum,
                                int nblocks, int n, int total) {
    __shared__ int pre[64];
    if (threadIdx.x == 0) {
        int s = 0;
        for (int b = 0; b < nblocks; b++) { pre[b] = s; s += bsum[b]; }
    }
    __syncthreads();
    int i = blockIdx.x * blockDim.x + threadIdx.x;
    if (i < n) off[i] += pre[i >> 10];
    if (i == 0) off[n] = total;
}

__global__ void scatter_kernel(const int* __restrict__ ei, int E, int n,
                               const int* __restrict__ off, int* __restrict__ fill,
                               int* __restrict__ csrc) {
    int i = blockIdx.x * blockDim.x + threadIdx.x;
    if (i >= E + n) return;
    int s, d;
    if (i < E) { s = ei[i]; d = ei[E + i]; } else { s = d = i - E; }
    int pos = off[d] + atomicAdd(&fill[d], 1);
    csrc[pos] = s;
}

// ------------------------- GAT pieces -------------------------
__global__ void node_dots_kernel(const float* __restrict__ x,
                                 const float* __restrict__ asrc,
                                 const float* __restrict__ adst,
                                 float* __restrict__ out_s, float* __restrict__ out_d,
                                 int n, int F) {
    int w = (int)((blockIdx.x * (size_t)blockDim.x + threadIdx.x) >> 5);
    int lane = threadIdx.x & 31;
    if (w >= n) return;
    const float* xr = x + (size_t)w * F;
    float s = 0.f, d = 0.f;
    for (int f = lane; f < F; f += 32) {
        float v = xr[f];
        s = fmaf(v, asrc[f], s);
        d = fmaf(v, adst[f], d);
    }
#pragma unroll
    for (int o = 16; o; o >>= 1) {
        s += __shfl_xor_sync(0xffffffffu, s, o);
        d += __shfl_xor_sync(0xffffffffu, d, o);
    }
    if (lane == 0) { out_s[w] = s; out_d[w] = d; }
}

// warp-per-node segment softmax over CSR edges; writes normalized alpha
__global__ void csr_softmax_kernel(const int* __restrict__ off, const int* __restrict__ csrc,
                                   const float* __restrict__ as_, const float* __restrict__ ad_,
                                   float* __restrict__ alpha, int n) {
    int w = (int)((blockIdx.x * (size_t)blockDim.x + threadIdx.x) >> 5);
    int lane = threadIdx.x & 31;
    if (w >= n) return;
    int beg = off[w], end = off[w + 1];
    float add = ad_[w];
    float m = -1e30f;
    for (int j = beg + lane; j < end; j += 32) {
        float e = as_[csrc[j]] + add;
        e = e > 0.f ? e : 0.2f * e;
        m = fmaxf(m, e);
    }
#pragma unroll
    for (int o = 16; o; o >>= 1) m = fmaxf(m, __shfl_xor_sync(0xffffffffu, m, o));
    float s = 0.f;
    for (int j = beg + lane; j < end; j += 32) {
        float e = as_[csrc[j]] + add;
        e = e > 0.f ? e : 0.2f * e;
        float v = expf(e - m);
        alpha[j] = v;
        s += v;
    }
#pragma unroll
    for (int o = 16; o; o >>= 1) s += __shfl_xor_sync(0xffffffffu, s, o);
    float inv = 1.f / s;
    for (int j = beg + lane; j < end; j += 32) alpha[j] *= inv;
}

// block-per-node gather: out[d,:] = relu(sum_e alpha[e]*x[src[e],:] + bias)
template<int F>
__global__ void csr_gather_kernel(const int* __restrict__ off, const int* __restrict__ csrc,
                                  const float* __restrict__ alpha,
                                  const float* __restrict__ x,
                                  const float* __restrict__ bias,
                                  float* __restrict__ out) {
    constexpr int FPT = F / 256;
    int d = blockIdx.x;
    int t = threadIdx.x;
    int beg = off[d], end = off[d + 1];
    float acc[FPT];
#pragma unroll
    for (int q = 0; q < FPT; q++) acc[q] = 0.f;

    int j = beg;
    for (; j + 1 < end; j += 2) {
        int s0 = csrc[j], s1 = csrc[j + 1];
        float a0 = alpha[j], a1 = alpha[j + 1];
        const float* x0 = x + (size_t)s0 * F;
        const float* x1 = x + (size_t)s1 * F;
#pragma unroll
        for (int q = 0; q < FPT; q++)
            acc[q] = fmaf(a1, x1[t + q * 256], fmaf(a0, x0[t + q * 256], acc[q]));
    }
    if (j < end) {
        int s0 = csrc[j];
        float a0 = alpha[j];
        const float* x0 = x + (size_t)s0 * F;
#pragma unroll
        for (int q = 0; q < FPT; q++)
            acc[q] = fmaf(a0, x0[t + q * 256], acc[q]);
    }
    float* orow = out + (size_t)d * F;
#pragma unroll
    for (int q = 0; q < FPT; q++) {
        float v = acc[q] + bias[t + q * 256];
        orow[t + q * 256] = v > 0.f ? v : 0.f;
    }
}

// ------------------------- misc -------------------------
__global__ void gather_comb_kernel(const float* __restrict__ dsrc, const float* __restrict__ csrc,
                                   const int* __restrict__ di, const int* __restrict__ ci,
                                   float* __restrict__ comb) {
    int b = blockIdx.x;
    int t = threadIdx.x;
    comb[(size_t)b * 512 + t] = dsrc[(size_t)di[b] * 256 + t];
    comb[(size_t)b * 512 + 256 + t] = csrc[(size_t)ci[b] * 256 + t];
}

__global__ void head_final_kernel(const float* __restrict__ h, const float* __restrict__ W,
                                  const float* __restrict__ b, float* __restrict__ out) {
    size_t gt = blockIdx.x * (size_t)blockDim.x + threadIdx.x;
    int r = (int)(gt >> 5);
    int lane = threadIdx.x & 31;
    if (r >= BATCH) return;
    const float* hr = h + (size_t)r * 512;
    float s = 0.f;
    for (int f = lane; f < 512; f += 32) s = fmaf(hr[f], W[f], s);
#pragma unroll
    for (int o = 16; o; o >>= 1) s += __shfl_xor_sync(0xffffffffu, s, o);
    if (lane == 0) out[r] = s + b[0];
}

// ------------------------- host side -------------------------
static void build_csr(const int* ei, int E, int n, int* cnt, int* off, int* bsum, int* csrc) {
    cudaMemsetAsync(cnt, 0, n * sizeof(int));
    int total = E + n;
    hist_kernel<<<(total + 255) / 256, 256>>>(ei, E, n, cnt);
    int nblocks = (n + 1023) / 1024;
    scan_block_kernel<<<nblocks, 1024>>>(cnt, off, bsum, n);
    scan_add_kernel<<<(n + 255) / 256, 256>>>(off, bsum, nblocks, n, total);
    cudaMemsetAsync(cnt, 0, n * sizeof(int));
    scatter_kernel<<<(total + 255) / 256, 256>>>(ei, E, n, off, cnt, csrc);
}

static void run_gat_csr(const int* off, const int* csrc, int n, int F,
                        const float* x, const float* avec_s, const float* avec_d,
                        const float* bias, float* as_, float* ad_, float* alpha, float* out) {
    size_t threads = (size_t)n * 32;
    node_dots_kernel<<<(unsigned)((threads + 255) / 256), 256>>>(x, avec_s, avec_d, as_, ad_, n, F);
    csr_softmax_kernel<<<(unsigned)((threads + 255) / 256), 256>>>(off, csrc, as_, ad_, alpha, n);
    if (F == 1024)
        csr_gather_kernel<1024><<<n, 256>>>(off, csrc, alpha, x, bias, out);
    else
        csr_gather_kernel<256><<<n, 256>>>(off, csrc, alpha, x, bias, out);
}

extern "C" void kernel_launch(void* const* d_in, const int* in_sizes, int n_in,
                              void* d_out, int out_size) {
    const float* drug_x = (const float*)d_in[0];
    const float* cell_x = (const float*)d_in[1];
    const int* dei = (const int*)d_in[2];
    const int* cei = (const int*)d_in[3];
    const int* didx = (const int*)d_in[4];
    const int* cidx = (const int*)d_in[5];
    const float* dW1 = (const float*)d_in[6];  const float* db1 = (const float*)d_in[7];
    const float* cW1 = (const float*)d_in[8];  const float* cb1 = (const float*)d_in[9];
    const float* cW2 = (const float*)d_in[10]; const float* cb2 = (const float*)d_in[11];
    const float* gdW = (const float*)d_in[12]; const float* gdas = (const float*)d_in[13];
    const float* gdad = (const float*)d_in[14]; const float* gdb = (const float*)d_in[15];
    const float* g1W = (const float*)d_in[16]; const float* g1as = (const float*)d_in[17];
    const float* g1ad = (const float*)d_in[18]; const float* g1b = (const float*)d_in[19];
    const float* g2W = (const float*)d_in[20]; const float* g2as = (const float*)d_in[21];
    const float* g2ad = (const float*)d_in[22]; const float* g2b = (const float*)d_in[23];
    const float* rW1 = (const float*)d_in[24]; const float* rb1 = (const float*)d_in[25];
    const float* rW2 = (const float*)d_in[26]; const float* rb2 = (const float*)d_in[27];
    const float* rW3 = (const float*)d_in[28]; const float* rb3 = (const float*)d_in[29];
    float* out = (float*)d_out;

    float *p_d0, *p_dx, *p_dagg, *p_c0, *p_c1, *p_cx1, *p_cagg1, *p_cx2, *p_cagg2;
    float *p_as, *p_ad, *p_alpha, *p_cxp, *p_w1p, *p_comb, *p_h1, *p_h2;
    int *p_off, *p_cnt, *p_bsum, *p_csrc;
    cudaGetSymbolAddress((void**)&p_d0, g_d0);
    cudaGetSymbolAddress((void**)&p_dx, g_dx);
    cudaGetSymbolAddress((void**)&p_dagg, g_dagg);
    cudaGetSymbolAddress((void**)&p_c0, g_c0);
    cudaGetSymbolAddress((void**)&p_c1, g_c1);
    cudaGetSymbolAddress((void**)&p_cx1, g_cx1);
    cudaGetSymbolAddress((void**)&p_cagg1, g_cagg1);
    cudaGetSymbolAddress((void**)&p_cx2, g_cx2);
    cudaGetSymbolAddress((void**)&p_cagg2, g_cagg2);
    cudaGetSymbolAddress((void**)&p_as, g_as);
    cudaGetSymbolAddress((void**)&p_ad, g_ad);
    cudaGetSymbolAddress((void**)&p_alpha, g_alpha);
    cudaGetSymbolAddress((void**)&p_off, g_off);
    cudaGetSymbolAddress((void**)&p_cnt, g_cnt);
    cudaGetSymbolAddress((void**)&p_bsum, g_bsum);
    cudaGetSymbolAddress((void**)&p_csrc, g_csrc);
    cudaGetSymbolAddress((void**)&p_cxp, g_cxp);
    cudaGetSymbolAddress((void**)&p_w1p, g_w1p);
    cudaGetSymbolAddress((void**)&p_comb, g_comb);
    cudaGetSymbolAddress((void**)&p_h1, g_h1);
    cudaGetSymbolAddress((void**)&p_h2, g_h2);

    // ---- padding for K=735 GEMM ----
    pad_cellx_kernel<<<(NC * FCP + 255) / 256, 256>>>(cell_x, p_cxp);
    pad_w1_kernel<<<(FCP * 1024 + 255) / 256, 256>>>(cW1, p_w1p);

    // ---- feature transforms ----
    sgemm128(drug_x, dW1, db1, p_d0, ND, 256, FD, 1);
    sgemm128(p_cxp, p_w1p, cb1, p_c0, NC, 1024, FCP, 1);
    sgemm64(p_c0, cW2, cb2, p_c1, NC, 256, 1024, 1);

    // ---- drug GAT (256 -> 256) ----
    sgemm128(p_d0, gdW, nullptr, p_dx, ND, 256, 256, 0);
    build_csr(dei, ED, ND, p_cnt, p_off, p_bsum, p_csrc);
    run_gat_csr(p_off, p_csrc, ND, 256, p_dx, gdas, gdad, gdb, p_as, p_ad, p_alpha, p_dagg);

    // ---- cell GAT1 (256 -> 1024) ----
    sgemm128(p_c1, g1W, nullptr, p_cx1, NC, 1024, 256, 0);
    build_csr(cei, EC, NC, p_cnt, p_off, p_bsum, p_csrc);   // shared by GAT1 + GAT2
    run_gat_csr(p_off, p_csrc, NC, 1024, p_cx1, g1as, g1ad, g1b, p_as, p_ad, p_alpha, p_cagg1);

    // ---- cell GAT2 (1024 -> 256) ----
    sgemm64(p_cagg1, g2W, nullptr, p_cx2, NC, 256, 1024, 0);
    run_gat_csr(p_off, p_csrc, NC, 256, p_cx2, g2as, g2ad, g2b, p_as, p_ad, p_alpha, p_cagg2);

    // ---- pair gather + regression head ----
    gather_comb_kernel<<<BATCH, 256>>>(p_dagg, p_cagg2, didx, cidx, p_comb);
    sgemm128(p_comb, rW1, rb1, p_h1, BATCH, 512, 512, 2);
    sgemm128(p_h1, rW2, rb2, p_h2, BATCH, 512, 512, 2);
    head_final_kernel<<<(BATCH * 32 + 255) / 256, 256>>>(p_h2, rW3, rb3, out);
}